// round 5
// baseline (speedup 1.0000x reference)
#include <cuda_runtime.h>
#include <cuda_fp16.h>
#include <cstdint>
#include <cstddef>

#define NROWS 8192
#define DIN   2048
#define DOUT  2048

#define BM 128
#define BN 128
#define BK 32
#define NCHUNK (DIN / BK)          // 64
#define NT_M (NROWS / BM)          // 64
#define NT_N (DOUT / BN)           // 16

#define PITCH 40                   // halves per smem row (80 bytes) -> conflict-free ldmatrix
#define TILE_H (BM * PITCH)        // 5120 halves per tile-buffer
#define TILE_BYTES (TILE_H * 2)    // 10240 bytes

__device__ __align__(16) __half g_Ah[(size_t)NROWS * DIN];  // 32 MB
__device__ __align__(16) __half g_Bt[(size_t)DOUT * DIN];   // 8 MB, Bt[n][k] = sign(W[k][n])

static __device__ __forceinline__ uint32_t smem_u32(const void* p) {
    uint32_t a;
    asm("{ .reg .u64 t; cvta.to.shared.u64 t, %1; cvt.u32.u64 %0, t; }" : "=r"(a) : "l"(p));
    return a;
}
static __device__ __forceinline__ uint32_t pack2(float a, float b) {
    __half2 h = __floats2half2_rn(a, b);
    return *reinterpret_cast<uint32_t*>(&h);
}
static __device__ __forceinline__ void cp16(uint32_t dst, const void* src) {
    asm volatile("cp.async.cg.shared.global [%0], [%1], 16;" :: "r"(dst), "l"(src));
}
#define CP_COMMIT() asm volatile("cp.async.commit_group;" ::: "memory")
#define CP_WAIT1()  asm volatile("cp.async.wait_group 1;" ::: "memory")

#define LDSM_X4(r0, r1, r2, r3, addr) \
    asm volatile("ldmatrix.sync.aligned.m8n8.x4.shared.b16 {%0,%1,%2,%3}, [%4];" \
                 : "=r"(r0), "=r"(r1), "=r"(r2), "=r"(r3) : "r"(addr))

#define MMA16816(c, a, b0, b1) \
    asm volatile("mma.sync.aligned.m16n8k16.row.col.f32.f16.f16.f32 " \
                 "{%0,%1,%2,%3}, {%4,%5,%6,%7}, {%8,%9}, {%0,%1,%2,%3};" \
                 : "+f"((c)[0]), "+f"((c)[1]), "+f"((c)[2]), "+f"((c)[3]) \
                 : "r"((a)[0]), "r"((a)[1]), "r"((a)[2]), "r"((a)[3]), \
                   "r"(b0), "r"(b1))

// ---------------- prepA: A fp32 -> fp16, row-major ----------------
__global__ __launch_bounds__(256) void prepA_kernel(const float* __restrict__ A) {
    const size_t i = ((size_t)blockIdx.x * 256 + threadIdx.x) * 8;
    const float4* src = reinterpret_cast<const float4*>(A + i);
    float4 f0 = src[0], f1 = src[1];
    uint4 u;
    u.x = pack2(f0.x, f0.y); u.y = pack2(f0.z, f0.w);
    u.z = pack2(f1.x, f1.y); u.w = pack2(f1.z, f1.w);
    *reinterpret_cast<uint4*>(g_Ah + i) = u;
}

// ------- prepB: Bt[n][k] = sign(W[k][n]) as fp16 (32x32 smem transpose) -------
__global__ __launch_bounds__(256) void prepB_kernel(const float* __restrict__ W) {
    __shared__ __half s[32][33];
    const int nb = (int)blockIdx.x % (DOUT / 32);
    const int kb = (int)blockIdx.x / (DOUT / 32);
    const int tx = threadIdx.x & 31, ty = threadIdx.x >> 5;  // 32 x 8
    #pragma unroll
    for (int j = 0; j < 4; j++) {
        const int kk = ty + j * 8;
        const float w = W[(size_t)(kb * 32 + kk) * DOUT + nb * 32 + tx];
        s[kk][tx] = __float2half_rn(w > 0.f ? 1.f : (w < 0.f ? -1.f : 0.f));
    }
    __syncthreads();
    #pragma unroll
    for (int j = 0; j < 4; j++) {
        const int nn = ty + j * 8;
        g_Bt[(size_t)(nb * 32 + nn) * DIN + kb * 32 + tx] = s[tx][nn];
    }
}

// -------------------------------- GEMM --------------------------------
// smem: As[2][128][40] | Bs[2][128][40]  (halves) = 40960 bytes
__global__ __launch_bounds__(256, 2) void gemm_kernel(const float* __restrict__ bias,
                                                      float* __restrict__ out) {
    __shared__ __align__(16) __half sm[4 * TILE_H];
    const uint32_t sA = smem_u32(sm);                    // + buf*TILE_BYTES
    const uint32_t sB = sA + 2 * TILE_BYTES;             // + buf*TILE_BYTES

    const int tid = threadIdx.x;
    const int lid = tid & 31;
    const int warp = tid >> 5;
    const int warp_m = warp & 3;      // 4 warps in m
    const int warp_n = warp >> 2;     // 2 warps in n
    const int mt = (int)blockIdx.x & 63;
    const int nt = (int)blockIdx.x >> 6;
    const int m0 = mt * BM, n0 = nt * BN;

    // cp.async chunk mapping: 512 16B-chunks per tile, 2 per thread
    const int c0 = tid, c1 = tid + 256;
    const int ar0 = c0 >> 2, as0 = c0 & 3;
    const int ar1 = c1 >> 2, as1 = c1 & 3;

    // ldmatrix source addresses (buf 0)
    const int g = lid >> 3, lr = lid & 7;
    uint32_t a_addr[2][2], b_addr[4][2];
    #pragma unroll
    for (int mf = 0; mf < 2; mf++)
        #pragma unroll
        for (int kh = 0; kh < 2; kh++) {
            const int row = warp_m * 32 + mf * 16 + (g & 1) * 8 + lr;
            const int col = kh * 16 + (g >> 1) * 8;
            a_addr[mf][kh] = sA + (uint32_t)(row * PITCH + col) * 2;
        }
    #pragma unroll
    for (int nf2 = 0; nf2 < 4; nf2++)
        #pragma unroll
        for (int kh = 0; kh < 2; kh++) {
            const int row = warp_n * 64 + nf2 * 16 + (g >> 1) * 8 + lr;
            const int col = kh * 16 + (g & 1) * 8;
            b_addr[nf2][kh] = sB + (uint32_t)(row * PITCH + col) * 2;
        }

    // bias values for this thread's output columns
    float2 bv[8];
    #pragma unroll
    for (int nf = 0; nf < 8; nf++) {
        const int col = n0 + warp_n * 64 + nf * 8 + (lid & 3) * 2;
        bv[nf] = *reinterpret_cast<const float2*>(bias + col);
    }

    float c[2][8][4];
    #pragma unroll
    for (int mf = 0; mf < 2; mf++)
        #pragma unroll
        for (int nf = 0; nf < 8; nf++)
            #pragma unroll
            for (int q = 0; q < 4; q++) c[mf][nf][q] = 0.f;

    const __half* gA = g_Ah + (size_t)m0 * DIN;
    const __half* gB = g_Bt + (size_t)n0 * DIN;

    // prefetch chunk 0 into buf 0
    {
        cp16(sA + (uint32_t)(ar0 * PITCH + as0 * 8) * 2, gA + (size_t)ar0 * DIN + as0 * 8);
        cp16(sA + (uint32_t)(ar1 * PITCH + as1 * 8) * 2, gA + (size_t)ar1 * DIN + as1 * 8);
        cp16(sB + (uint32_t)(ar0 * PITCH + as0 * 8) * 2, gB + (size_t)ar0 * DIN + as0 * 8);
        cp16(sB + (uint32_t)(ar1 * PITCH + as1 * 8) * 2, gB + (size_t)ar1 * DIN + as1 * 8);
    }
    CP_COMMIT();

    for (int kc = 0; kc < NCHUNK; kc++) {
        const int buf = kc & 1;
        if (kc + 1 < NCHUNK) {
            const uint32_t off = (uint32_t)((kc + 1) & 1) * TILE_BYTES;
            const int k1 = (kc + 1) * BK;
            cp16(sA + off + (uint32_t)(ar0 * PITCH + as0 * 8) * 2,
                 gA + (size_t)ar0 * DIN + k1 + as0 * 8);
            cp16(sA + off + (uint32_t)(ar1 * PITCH + as1 * 8) * 2,
                 gA + (size_t)ar1 * DIN + k1 + as1 * 8);
            cp16(sB + off + (uint32_t)(ar0 * PITCH + as0 * 8) * 2,
                 gB + (size_t)ar0 * DIN + k1 + as0 * 8);
            cp16(sB + off + (uint32_t)(ar1 * PITCH + as1 * 8) * 2,
                 gB + (size_t)ar1 * DIN + k1 + as1 * 8);
        }
        CP_COMMIT();
        CP_WAIT1();
        __syncthreads();

        const uint32_t boff = (uint32_t)buf * TILE_BYTES;
        #pragma unroll
        for (int kh = 0; kh < 2; kh++) {
            uint32_t a[2][4];
            LDSM_X4(a[0][0], a[0][1], a[0][2], a[0][3], a_addr[0][kh] + boff);
            LDSM_X4(a[1][0], a[1][1], a[1][2], a[1][3], a_addr[1][kh] + boff);
            #pragma unroll
            for (int nf2 = 0; nf2 < 4; nf2++) {
                uint32_t b0, b1, b2, b3;
                LDSM_X4(b0, b1, b2, b3, b_addr[nf2][kh] + boff);
                MMA16816(c[0][nf2 * 2 + 0], a[0], b0, b1);
                MMA16816(c[1][nf2 * 2 + 0], a[1], b0, b1);
                MMA16816(c[0][nf2 * 2 + 1], a[0], b2, b3);
                MMA16816(c[1][nf2 * 2 + 1], a[1], b2, b3);
            }
        }
        __syncthreads();
    }

    // epilogue: bias + direct sector-aligned float2 stores
    #pragma unroll
    for (int mf = 0; mf < 2; mf++) {
        const int r0 = m0 + warp_m * 32 + mf * 16 + (lid >> 2);
        #pragma unroll
        for (int nf = 0; nf < 8; nf++) {
            const int col = n0 + warp_n * 64 + nf * 8 + (lid & 3) * 2;
            float2 v0 = make_float2(c[mf][nf][0] + bv[nf].x, c[mf][nf][1] + bv[nf].y);
            float2 v1 = make_float2(c[mf][nf][2] + bv[nf].x, c[mf][nf][3] + bv[nf].y);
            *reinterpret_cast<float2*>(out + (size_t)r0 * DOUT + col) = v0;
            *reinterpret_cast<float2*>(out + (size_t)(r0 + 8) * DOUT + col) = v1;
        }
    }
}

extern "C" void kernel_launch(void* const* d_in, const int* in_sizes, int n_in,
                              void* d_out, int out_size) {
    const float* A = (const float*)d_in[0];
    const float* W = (const float*)d_in[1];
    const float* b = (const float*)d_in[2];
    float* out = (float*)d_out;

    prepA_kernel<<<(NROWS * DIN) / (256 * 8), 256>>>(A);
    prepB_kernel<<<(DIN / 32) * (DOUT / 32), 256>>>(W);
    gemm_kernel<<<NT_M * NT_N, 256>>>(b, out);
}